// round 13
// baseline (speedup 1.0000x reference)
#include <cuda_runtime.h>
#include <cuda_bf16.h>
#include <cstdint>

// Problem constants
#define B_   4
#define S_   2048
#define D_   1024
#define H_   16
#define DH_  64
#define M_   (B_ * S_)       // 8192
#define NQKV (3 * D_)        // 3072
#define QKV_ELEMS (B_ * H_ * S_ * DH_)

// GEMM tiling (bf16-plane mainloop, 256 threads, 64x32 warp tiles, BK=64)
#define BM 128
#define BN 128
#define BK  64
#define AHSTR 72             // A plane smem row stride (bf16): 64 + 8 pad
#define BHSTR 136            // B plane smem row stride (bf16): 128 + 8 pad
#define APLANE 18432         // 128*72*2
#define BPLANE 17408         // 64*136*2
#define STAGE_BYTES (2 * APLANE + 2 * BPLANE)   // 71680
#define NSTAGE 3
#define GEMM_SMEM_BYTES (NSTAGE * STAGE_BYTES)  // 215040

// Attention smem: Q planes + double-buffered K/V planes (unchanged)
#define QSTR 72
#define QPLANE (128 * QSTR * 2)      // 18432 bytes per Q plane
#define KVPLANE (64 * QSTR * 2)      // 9216 bytes per K/V plane
#define KVBUF (4 * KVPLANE)          // 36864 bytes (Kh,Kl,Vh,Vl)
#define ATTN_SMEM_BYTES (2 * QPLANE + 2 * KVBUF)   // 110592

// Persistent bf16 hi/lo planes (allocation-free rule: __device__ globals)
__device__ __nv_bfloat16 g_Xh[M_ * D_], g_Xl[M_ * D_];
__device__ __nv_bfloat16 g_Wh[D_ * NQKV], g_Wl[D_ * NQKV];    // [k][n]
__device__ __nv_bfloat16 g_WOh[D_ * D_], g_WOl[D_ * D_];      // [k][n]
__device__ __nv_bfloat16 g_Qh[QKV_ELEMS], g_Ql[QKV_ELEMS];
__device__ __nv_bfloat16 g_Kh[QKV_ELEMS], g_Kl[QKV_ELEMS];
__device__ __nv_bfloat16 g_Vh[QKV_ELEMS], g_Vl[QKV_ELEMS];
__device__ __nv_bfloat16 g_Oh[QKV_ELEMS], g_Ol[QKV_ELEMS];

__device__ __forceinline__ uint32_t smem_u32(const void* p) {
  return (uint32_t)__cvta_generic_to_shared(p);
}
__device__ __forceinline__ void cp_async16(uint32_t dst, const void* src) {
  asm volatile("cp.async.cg.shared.global [%0], [%1], 16;\n" ::"r"(dst), "l"(src));
}
__device__ __forceinline__ void cp_commit() {
  asm volatile("cp.async.commit_group;\n");
}
template <int N>
__device__ __forceinline__ void cp_wait() {
  asm volatile("cp.async.wait_group %0;\n" ::"n"(N));
}

__device__ __forceinline__ void ldmatrix_x4(uint32_t* r, uint32_t addr) {
  asm volatile(
      "ldmatrix.sync.aligned.m8n8.x4.shared.b16 {%0,%1,%2,%3}, [%4];\n"
      : "=r"(r[0]), "=r"(r[1]), "=r"(r[2]), "=r"(r[3])
      : "r"(addr));
}
__device__ __forceinline__ void ldmatrix_x2(uint32_t* r, uint32_t addr) {
  asm volatile(
      "ldmatrix.sync.aligned.m8n8.x2.shared.b16 {%0,%1}, [%2];\n"
      : "=r"(r[0]), "=r"(r[1])
      : "r"(addr));
}
__device__ __forceinline__ void ldmatrix_x2_trans(uint32_t* r, uint32_t addr) {
  asm volatile(
      "ldmatrix.sync.aligned.m8n8.x2.trans.shared.b16 {%0,%1}, [%2];\n"
      : "=r"(r[0]), "=r"(r[1])
      : "r"(addr));
}
__device__ __forceinline__ void ldmatrix_x4_trans(uint32_t* r, uint32_t addr) {
  asm volatile(
      "ldmatrix.sync.aligned.m8n8.x4.trans.shared.b16 {%0,%1,%2,%3}, [%4];\n"
      : "=r"(r[0]), "=r"(r[1]), "=r"(r[2]), "=r"(r[3])
      : "r"(addr));
}

__device__ __forceinline__ void mma_bf16(float* c, const uint32_t* a,
                                         uint32_t b0, uint32_t b1) {
  asm volatile(
      "mma.sync.aligned.m16n8k16.row.col.f32.bf16.bf16.f32 "
      "{%0,%1,%2,%3}, {%4,%5,%6,%7}, {%8,%9}, {%0,%1,%2,%3};\n"
      : "+f"(c[0]), "+f"(c[1]), "+f"(c[2]), "+f"(c[3])
      : "r"(a[0]), "r"(a[1]), "r"(a[2]), "r"(a[3]), "r"(b0), "r"(b1));
}

// bf16 split-pack: hi pair returned (f0 low half), lo pair in lo_out.
__device__ __forceinline__ uint32_t pack_split_bf16(float f0, float f1,
                                                    uint32_t& lo_out) {
  uint32_t hi;
  asm("cvt.rn.bf16x2.f32 %0, %1, %2;\n" : "=r"(hi) : "f"(f1), "f"(f0));
  const float h0 = __uint_as_float(hi << 16);
  const float h1 = __uint_as_float(hi & 0xFFFF0000u);
  const float l0 = f0 - h0;
  const float l1 = f1 - h1;
  asm("cvt.rn.bf16x2.f32 %0, %1, %2;\n" : "=r"(lo_out) : "f"(l1), "f"(l0));
  return hi;
}

// ---------------------------------------------------------------------------
// Prepack: fp32 -> bf16 hi/lo planes.
// ---------------------------------------------------------------------------
__global__ void split_kernel(const float* __restrict__ in,
                             __nv_bfloat16* __restrict__ hi,
                             __nv_bfloat16* __restrict__ lo) {
  const int i = blockIdx.x * blockDim.x + threadIdx.x;
  const float2 v = ((const float2*)in)[i];
  uint32_t l;
  const uint32_t h = pack_split_bf16(v.x, v.y, l);
  ((uint32_t*)hi)[i] = h;
  ((uint32_t*)lo)[i] = l;
}

// ---------------------------------------------------------------------------
// bf16x3 GEMM mainloop: 256 threads, 8 warps (64x32 warp tile), BK=64,
// 3 smem stages, explicit 2-deep register fragment pipeline across ks.
// A planes [M][K], B planes [K][N].
// ---------------------------------------------------------------------------
struct MmaCtx {
  float acc[4][4][4];
};

template <int K, int N>
__device__ __forceinline__ void bf16_mainloop(
    const __nv_bfloat16* __restrict__ Ahp, const __nv_bfloat16* __restrict__ Alp,
    const __nv_bfloat16* __restrict__ Bhp, const __nv_bfloat16* __restrict__ Blp,
    int m0, int n0, char* sm, MmaCtx& ctx) {
  const int tid = threadIdx.x;
  const int lane = tid & 31;
  const int wid = tid >> 5;
  const int wm = wid & 1;   // 0..1 (64-row slabs)
  const int wn = wid >> 1;  // 0..3 (32-col slabs)

#pragma unroll
  for (int mt = 0; mt < 4; mt++)
#pragma unroll
    for (int nt = 0; nt < 4; nt++)
#pragma unroll
      for (int r = 0; r < 4; r++) ctx.acc[mt][nt][r] = 0.f;

  const int kTiles = K / BK;

  auto load_stage = [&](int t, int buf) {
    const int k0 = t * BK;
    const uint32_t base = smem_u32(sm) + (uint32_t)buf * STAGE_BYTES;
#pragma unroll
    for (int i = 0; i < 4; i++) {
      const int idx = tid + i * 256;
      const int ar = idx >> 3, akc = (idx & 7) * 8;
      cp_async16(base + (ar * AHSTR + akc) * 2,
                 Ahp + (size_t)(m0 + ar) * K + k0 + akc);
      cp_async16(base + APLANE + (ar * AHSTR + akc) * 2,
                 Alp + (size_t)(m0 + ar) * K + k0 + akc);
      const int br = idx >> 4, bnc = (idx & 15) * 8;
      cp_async16(base + 2 * APLANE + (br * BHSTR + bnc) * 2,
                 Bhp + (size_t)(k0 + br) * N + n0 + bnc);
      cp_async16(base + 2 * APLANE + BPLANE + (br * BHSTR + bnc) * 2,
                 Blp + (size_t)(k0 + br) * N + n0 + bnc);
    }
    cp_commit();
  };

  load_stage(0, 0);
  load_stage(1, 1);

  const int lrow = lane & 15;
  const int lseg = (lane >> 4) * 8;
  const int bkrow = ((lane >> 3) & 1) * 8 + (lane & 7);
  const int bnseg = (lane >> 4) * 8;

  // Double-buffered register fragments
  uint32_t ah[2][4][4], al[2][4][4], bh[2][4][2], bl[2][4][2];

  for (int t = 0; t < kTiles; t++) {
    const int buf = t % NSTAGE;
    if (t + 2 < kTiles) cp_wait<1>();
    else cp_wait<0>();
    __syncthreads();   // stage t visible; all warps done reading buf (t-1)

    if (t + 2 < kTiles) load_stage(t + 2, (t + 2) % NSTAGE);

    const uint32_t ahu = smem_u32(sm) + (uint32_t)buf * STAGE_BYTES;
    const uint32_t alu = ahu + APLANE;
    const uint32_t bhu = ahu + 2 * APLANE;
    const uint32_t blu = bhu + BPLANE;

    // Fragment loader for k-step ks into register buffer pb.
    auto load_frags = [&](int ks, int pb) {
#pragma unroll
      for (int mt = 0; mt < 4; mt++) {
        const int row = wm * 64 + mt * 16 + lrow;
        const uint32_t off = (uint32_t)(row * AHSTR + ks * 16 + lseg) * 2;
        ldmatrix_x4(ah[pb][mt], ahu + off);
        ldmatrix_x4(al[pb][mt], alu + off);
      }
#pragma unroll
      for (int np = 0; np < 2; np++) {
        const uint32_t off =
            (uint32_t)((ks * 16 + bkrow) * BHSTR + wn * 32 + np * 16 + bnseg) * 2;
        uint32_t rh[4], rl[4];
        ldmatrix_x4_trans(rh, bhu + off);
        ldmatrix_x4_trans(rl, blu + off);
        bh[pb][2 * np][0] = rh[0]; bh[pb][2 * np][1] = rh[1];
        bh[pb][2 * np + 1][0] = rh[2]; bh[pb][2 * np + 1][1] = rh[3];
        bl[pb][2 * np][0] = rl[0]; bl[pb][2 * np][1] = rl[1];
        bl[pb][2 * np + 1][0] = rl[2]; bl[pb][2 * np + 1][1] = rl[3];
      }
    };

    load_frags(0, 0);
#pragma unroll
    for (int ks = 0; ks < 4; ks++) {
      const int cur = ks & 1;
      if (ks + 1 < 4) load_frags(ks + 1, cur ^ 1);
#pragma unroll
      for (int mt = 0; mt < 4; mt++)
#pragma unroll
        for (int nt = 0; nt < 4; nt++) {
          mma_bf16(ctx.acc[mt][nt], al[cur][mt], bh[cur][nt][0], bh[cur][nt][1]);
          mma_bf16(ctx.acc[mt][nt], ah[cur][mt], bl[cur][nt][0], bl[cur][nt][1]);
          mma_bf16(ctx.acc[mt][nt], ah[cur][mt], bh[cur][nt][0], bh[cur][nt][1]);
        }
    }
  }
}

// ---------------------------------------------------------------------------
// Kernel 1: qkv = x @ w_qkv + b_qkv -> bf16 hi/lo planes of Q(scaled),K,V
// ---------------------------------------------------------------------------
__global__ __launch_bounds__(256, 1) void qkv_gemm_kernel(
    const float* __restrict__ bias) {
  extern __shared__ char sm[];
  const int m0 = blockIdx.y * BM;
  const int n0 = blockIdx.x * BN;

  MmaCtx ctx;
  bf16_mainloop<D_, NQKV>(g_Xh, g_Xl, g_Wh, g_Wl, m0, n0, sm, ctx);

  const int lane = threadIdx.x & 31;
  const int wid = threadIdx.x >> 5;
  const int wm = wid & 1, wn = wid >> 1;

#pragma unroll
  for (int nt = 0; nt < 4; nt++) {
    const int n = n0 + wn * 32 + nt * 8 + (lane & 3) * 2;
    const int t = n >> 10;
    const int rem = n & 1023;
    const int h = rem >> 6;
    const int e = rem & 63;
    __nv_bfloat16* dh = (t == 0) ? g_Qh : (t == 1) ? g_Kh : g_Vh;
    __nv_bfloat16* dl = (t == 0) ? g_Ql : (t == 1) ? g_Kl : g_Vl;
    const float sc = (t == 0) ? 0.125f : 1.0f;
    const float bz0 = bias[n], bz1 = bias[n + 1];
#pragma unroll
    for (int mt = 0; mt < 4; mt++) {
      const int mbase = m0 + wm * 64 + mt * 16 + (lane >> 2);
#pragma unroll
      for (int half = 0; half < 2; half++) {
        const int m = mbase + half * 8;
        const int b = m >> 11;
        const int s = m & 2047;
        const float v0 = (ctx.acc[mt][nt][half * 2 + 0] + bz0) * sc;
        const float v1 = (ctx.acc[mt][nt][half * 2 + 1] + bz1) * sc;
        uint32_t lo;
        const uint32_t hi = pack_split_bf16(v0, v1, lo);
        const size_t idx = (((size_t)(b * H_ + h) * S_ + s) * DH_ + e) >> 1;
        ((uint32_t*)dh)[idx] = hi;
        ((uint32_t*)dl)[idx] = lo;
      }
    }
  }
}

// ---------------------------------------------------------------------------
// Kernel 3: out = O @ w_out + b_out (reads bf16 planes, writes fp32)
// ---------------------------------------------------------------------------
__global__ __launch_bounds__(256, 1) void out_gemm_kernel(
    const float* __restrict__ bias, float* __restrict__ out) {
  extern __shared__ char sm[];
  const int m0 = blockIdx.y * BM;
  const int n0 = blockIdx.x * BN;

  MmaCtx ctx;
  bf16_mainloop<D_, D_>(g_Oh, g_Ol, g_WOh, g_WOl, m0, n0, sm, ctx);

  const int lane = threadIdx.x & 31;
  const int wid = threadIdx.x >> 5;
  const int wm = wid & 1, wn = wid >> 1;

#pragma unroll
  for (int nt = 0; nt < 4; nt++) {
    const int n = n0 + wn * 32 + nt * 8 + (lane & 3) * 2;
    const float bz0 = bias[n], bz1 = bias[n + 1];
#pragma unroll
    for (int mt = 0; mt < 4; mt++) {
      const int mbase = m0 + wm * 64 + mt * 16 + (lane >> 2);
#pragma unroll
      for (int half = 0; half < 2; half++) {
        const int m = mbase + half * 8;
        float2 v;
        v.x = ctx.acc[mt][nt][half * 2 + 0] + bz0;
        v.y = ctx.acc[mt][nt][half * 2 + 1] + bz1;
        *(float2*)&out[(size_t)m * D_ + n] = v;
      }
    }
  }
}

// ---------------------------------------------------------------------------
// Kernel 2: causal flash attention, bf16x3, P in registers, double-buffered
// cp.async K/V loads (unchanged from R9-R11 winner).
// ---------------------------------------------------------------------------
__global__ __launch_bounds__(256, 1) void attn_kernel() {
  extern __shared__ char smc[];
  __nv_bfloat16* Qh = (__nv_bfloat16*)smc;
  __nv_bfloat16* Ql = (__nv_bfloat16*)(smc + QPLANE);
  const uint32_t qh_u = smem_u32(Qh), ql_u = smem_u32(Ql);
  const uint32_t kv_u = smem_u32(smc + 2 * QPLANE);

  const int tid = threadIdx.x;
  const int lane = tid & 31;
  const int w = tid >> 5;
  const int g = lane >> 2;
  const int t = lane & 3;
  const int qt = (int)gridDim.x - 1 - (int)blockIdx.x;
  const int q0 = qt * 128;
  const int bh = blockIdx.y;
  const int b = bh >> 4, h = bh & 15;
  const size_t base = (size_t)bh * S_ * DH_;

  auto load_kv = [&](int kt, int buf) {
    const int k0 = kt * 64;
    const uint32_t kb = kv_u + (uint32_t)buf * KVBUF;
#pragma unroll
    for (int it = 0; it < 8; it++) {
      const int idx = tid + it * 256;
      const int pl = idx >> 9;
      const int r = (idx >> 3) & 63, c = (idx & 7) * 8;
      const __nv_bfloat16* src = (pl == 0) ? g_Kh : (pl == 1) ? g_Kl
                               : (pl == 2) ? g_Vh : g_Vl;
      cp_async16(kb + (uint32_t)(pl * KVPLANE) + (uint32_t)(r * QSTR + c) * 2,
                 src + base + (size_t)(k0 + r) * DH_ + c);
    }
    cp_commit();
  };

  load_kv(0, 0);

#pragma unroll
  for (int it = 0; it < 8; it++) {
    const int idx = tid + it * 256;
    const int pl = idx >> 10;
    const int r = (idx >> 3) & 127, c = (idx & 7) * 8;
    const __nv_bfloat16* src = pl ? g_Ql : g_Qh;
    __nv_bfloat16* dst = pl ? Ql : Qh;
    *(uint4*)&dst[r * QSTR + c] = *(const uint4*)&src[base + (size_t)(q0 + r) * DH_ + c];
  }
  __syncthreads();

  uint32_t qfh[4][4], qfl[4][4];
  {
    const int row = w * 16 + (lane & 15);
    const int seg = (lane >> 4) * 8;
#pragma unroll
    for (int ks = 0; ks < 4; ks++) {
      const uint32_t off = (uint32_t)(row * QSTR + ks * 16 + seg) * 2;
      ldmatrix_x4(qfh[ks], qh_u + off);
      ldmatrix_x4(qfl[ks], ql_u + off);
    }
  }

  float m_a = -1e30f, m_b = -1e30f, l_a = 0.f, l_b = 0.f;
  float o[8][4];
#pragma unroll
  for (int nt = 0; nt < 8; nt++)
#pragma unroll
    for (int r = 0; r < 4; r++) o[nt][r] = 0.f;

  const int nkt = 2 * (qt + 1);
  for (int kt = 0; kt < nkt; kt++) {
    const int buf = kt & 1;
    cp_wait<0>();
    __syncthreads();

    if (kt + 1 < nkt) load_kv(kt + 1, buf ^ 1);

    const uint32_t kh_u = kv_u + (uint32_t)buf * KVBUF;
    const uint32_t kl_u = kh_u + KVPLANE;
    const uint32_t vh_u = kl_u + KVPLANE;
    const uint32_t vl_u = vh_u + KVPLANE;
    const int k0 = kt * 64;

    float s[8][4];
#pragma unroll
    for (int nt = 0; nt < 8; nt++) {
#pragma unroll
      for (int r = 0; r < 4; r++) s[nt][r] = 0.f;
      const uint32_t roff =
          (uint32_t)((nt * 8 + (lane & 7)) * QSTR + ((lane >> 3) & 1) * 8) * 2;
#pragma unroll
      for (int ks = 0; ks < 4; ks++) {
        uint32_t kbh[2], kbl[2];
        const uint32_t off = roff + (uint32_t)(ks * 16) * 2;
        ldmatrix_x2(kbh, kh_u + off);
        ldmatrix_x2(kbl, kl_u + off);
        mma_bf16(s[nt], qfl[ks], kbh[0], kbh[1]);
        mma_bf16(s[nt], qfh[ks], kbl[0], kbl[1]);
        mma_bf16(s[nt], qfh[ks], kbh[0], kbh[1]);
      }
    }

    const int lr = w * 16 + g;
    if (kt >= nkt - 2) {
      const int ra = q0 + lr, rb = ra + 8;
#pragma unroll
      for (int nt = 0; nt < 8; nt++) {
        const int c0 = k0 + nt * 8 + t * 2;
        if (c0 > ra) s[nt][0] = -1e30f;
        if (c0 + 1 > ra) s[nt][1] = -1e30f;
        if (c0 > rb) s[nt][2] = -1e30f;
        if (c0 + 1 > rb) s[nt][3] = -1e30f;
      }
    }

    float mxa = -1e30f, mxb = -1e30f;
#pragma unroll
    for (int nt = 0; nt < 8; nt++) {
      mxa = fmaxf(mxa, fmaxf(s[nt][0], s[nt][1]));
      mxb = fmaxf(mxb, fmaxf(s[nt][2], s[nt][3]));
    }
#pragma unroll
    for (int off = 1; off <= 2; off <<= 1) {
      mxa = fmaxf(mxa, __shfl_xor_sync(0xffffffffu, mxa, off));
      mxb = fmaxf(mxb, __shfl_xor_sync(0xffffffffu, mxb, off));
    }
    const float mna = fmaxf(m_a, mxa), mnb = fmaxf(m_b, mxb);
    const float sca = __expf(m_a - mna), scb = __expf(m_b - mnb);
    float rsa = 0.f, rsb = 0.f;
#pragma unroll
    for (int nt = 0; nt < 8; nt++) {
      s[nt][0] = __expf(s[nt][0] - mna);
      s[nt][1] = __expf(s[nt][1] - mna);
      s[nt][2] = __expf(s[nt][2] - mnb);
      s[nt][3] = __expf(s[nt][3] - mnb);
      rsa += s[nt][0] + s[nt][1];
      rsb += s[nt][2] + s[nt][3];
    }
#pragma unroll
    for (int off = 1; off <= 2; off <<= 1) {
      rsa += __shfl_xor_sync(0xffffffffu, rsa, off);
      rsb += __shfl_xor_sync(0xffffffffu, rsb, off);
    }
    l_a = l_a * sca + rsa;
    l_b = l_b * scb + rsb;
    m_a = mna;
    m_b = mnb;
#pragma unroll
    for (int nt = 0; nt < 8; nt++) {
      o[nt][0] *= sca; o[nt][1] *= sca;
      o[nt][2] *= scb; o[nt][3] *= scb;
    }

#pragma unroll
    for (int jt = 0; jt < 4; jt++) {
      uint32_t ph[4], pl[4];
      ph[0] = pack_split_bf16(s[2 * jt][0], s[2 * jt][1], pl[0]);
      ph[1] = pack_split_bf16(s[2 * jt][2], s[2 * jt][3], pl[1]);
      ph[2] = pack_split_bf16(s[2 * jt + 1][0], s[2 * jt + 1][1], pl[2]);
      ph[3] = pack_split_bf16(s[2 * jt + 1][2], s[2 * jt + 1][3], pl[3]);
      const uint32_t roff = (uint32_t)((jt * 16 + (lane & 15)) * QSTR) * 2;
#pragma unroll
      for (int nt = 0; nt < 8; nt++) {
        uint32_t vbh[2], vbl[2];
        const uint32_t off = roff + (uint32_t)(nt * 8) * 2;
        ldmatrix_x2_trans(vbh, vh_u + off);
        ldmatrix_x2_trans(vbl, vl_u + off);
        mma_bf16(o[nt], pl, vbh[0], vbh[1]);
        mma_bf16(o[nt], ph, vbl[0], vbl[1]);
        mma_bf16(o[nt], ph, vbh[0], vbh[1]);
      }
    }
  }

  const float ia = 1.f / l_a, ib = 1.f / l_b;
  const int lr = w * 16 + g;
  const int ra = q0 + lr, rb = ra + 8;
#pragma unroll
  for (int nt = 0; nt < 8; nt++) {
    const int e = nt * 8 + t * 2;
    uint32_t lo;
    uint32_t hi = pack_split_bf16(o[nt][0] * ia, o[nt][1] * ia, lo);
    size_t idx = (((size_t)(b * S_ + ra) * H_ + h) * DH_ + e) >> 1;
    ((uint32_t*)g_Oh)[idx] = hi;
    ((uint32_t*)g_Ol)[idx] = lo;
    hi = pack_split_bf16(o[nt][2] * ib, o[nt][3] * ib, lo);
    idx = (((size_t)(b * S_ + rb) * H_ + h) * DH_ + e) >> 1;
    ((uint32_t*)g_Oh)[idx] = hi;
    ((uint32_t*)g_Ol)[idx] = lo;
  }
}

// ---------------------------------------------------------------------------
extern "C" void kernel_launch(void* const* d_in, const int* in_sizes, int n_in,
                              void* d_out, int out_size) {
  const float* x     = (const float*)d_in[0];  // [B,S,D]
  const float* w_qkv = (const float*)d_in[1];  // [D,3,H,DH]
  const float* b_qkv = (const float*)d_in[2];  // [3,H,DH]
  const float* w_out = (const float*)d_in[3];  // [H,DH,D]
  const float* b_out = (const float*)d_in[4];  // [D]
  float* out = (float*)d_out;                  // [B,S,D]

  cudaFuncSetAttribute(qkv_gemm_kernel,
                       cudaFuncAttributeMaxDynamicSharedMemorySize,
                       GEMM_SMEM_BYTES);
  cudaFuncSetAttribute(out_gemm_kernel,
                       cudaFuncAttributeMaxDynamicSharedMemorySize,
                       GEMM_SMEM_BYTES);
  cudaFuncSetAttribute(attn_kernel, cudaFuncAttributeMaxDynamicSharedMemorySize,
                       ATTN_SMEM_BYTES);

  __nv_bfloat16 *xh, *xl, *wh, *wl, *woh, *wol;
  cudaGetSymbolAddress((void**)&xh, g_Xh);
  cudaGetSymbolAddress((void**)&xl, g_Xl);
  cudaGetSymbolAddress((void**)&wh, g_Wh);
  cudaGetSymbolAddress((void**)&wl, g_Wl);
  cudaGetSymbolAddress((void**)&woh, g_WOh);
  cudaGetSymbolAddress((void**)&wol, g_WOl);

  split_kernel<<<(M_ * D_ / 2) / 256, 256>>>(x, xh, xl);
  split_kernel<<<(D_ * NQKV / 2) / 256, 256>>>(w_qkv, wh, wl);
  split_kernel<<<(D_ * D_ / 2) / 256, 256>>>(w_out, woh, wol);

  qkv_gemm_kernel<<<dim3(NQKV / BN, M_ / BM), 256, GEMM_SMEM_BYTES>>>(b_qkv);
  attn_kernel<<<dim3(S_ / 128, B_ * H_), 256, ATTN_SMEM_BYTES>>>();
  out_gemm_kernel<<<dim3(D_ / BN, M_ / BM), 256, GEMM_SMEM_BYTES>>>(b_out, out);
}

// round 16
// speedup vs baseline: 1.0240x; 1.0240x over previous
#include <cuda_runtime.h>
#include <cuda_bf16.h>
#include <cstdint>

// Problem constants
#define B_   4
#define S_   2048
#define D_   1024
#define H_   16
#define DH_  64
#define M_   (B_ * S_)       // 8192
#define NQKV (3 * D_)        // 3072
#define QKV_ELEMS (B_ * H_ * S_ * DH_)

// GEMM tiling (R11 winner: 256 threads, 64x32 warp tiles, BK=64, 3 stages)
#define BM 128
#define BN 128
#define BK  64
#define AHSTR 72             // A plane smem row stride (bf16): 64 + 8 pad
#define BHSTR 136            // B plane smem row stride (bf16): 128 + 8 pad
#define APLANE 18432         // 128*72*2
#define BPLANE 17408         // 64*136*2
#define STAGE_BYTES (2 * APLANE + 2 * BPLANE)   // 71680
#define NSTAGE 3
#define GEMM_SMEM_BYTES (NSTAGE * STAGE_BYTES)  // 215040

// Attention smem: Q planes + double-buffered 128-row K/V planes
#define QSTR 72
#define QPLANE (128 * QSTR * 2)      // 18432 bytes per Q plane
#define KVPLANE (128 * QSTR * 2)     // 18432 bytes per K/V plane (128 rows)
#define KVBUF (4 * KVPLANE)          // 73728 bytes (Kh,Kl,Vh,Vl)
#define KVHALF (64 * QSTR * 2)       // 9216: byte offset of second 64-row half
#define ATTN_SMEM_BYTES (2 * QPLANE + 2 * KVBUF)   // 184320

// Persistent bf16 hi/lo planes (allocation-free rule: __device__ globals)
__device__ __nv_bfloat16 g_Xh[M_ * D_], g_Xl[M_ * D_];
__device__ __nv_bfloat16 g_Wh[D_ * NQKV], g_Wl[D_ * NQKV];    // [k][n]
__device__ __nv_bfloat16 g_WOh[D_ * D_], g_WOl[D_ * D_];      // [k][n]
__device__ __nv_bfloat16 g_Qh[QKV_ELEMS], g_Ql[QKV_ELEMS];
__device__ __nv_bfloat16 g_Kh[QKV_ELEMS], g_Kl[QKV_ELEMS];
__device__ __nv_bfloat16 g_Vh[QKV_ELEMS], g_Vl[QKV_ELEMS];
__device__ __nv_bfloat16 g_Oh[QKV_ELEMS], g_Ol[QKV_ELEMS];

__device__ __forceinline__ uint32_t smem_u32(const void* p) {
  return (uint32_t)__cvta_generic_to_shared(p);
}
__device__ __forceinline__ void cp_async16(uint32_t dst, const void* src) {
  asm volatile("cp.async.cg.shared.global [%0], [%1], 16;\n" ::"r"(dst), "l"(src));
}
__device__ __forceinline__ void cp_commit() {
  asm volatile("cp.async.commit_group;\n");
}
template <int N>
__device__ __forceinline__ void cp_wait() {
  asm volatile("cp.async.wait_group %0;\n" ::"n"(N));
}

__device__ __forceinline__ void ldmatrix_x4(uint32_t* r, uint32_t addr) {
  asm volatile(
      "ldmatrix.sync.aligned.m8n8.x4.shared.b16 {%0,%1,%2,%3}, [%4];\n"
      : "=r"(r[0]), "=r"(r[1]), "=r"(r[2]), "=r"(r[3])
      : "r"(addr));
}
__device__ __forceinline__ void ldmatrix_x2(uint32_t* r, uint32_t addr) {
  asm volatile(
      "ldmatrix.sync.aligned.m8n8.x2.shared.b16 {%0,%1}, [%2];\n"
      : "=r"(r[0]), "=r"(r[1])
      : "r"(addr));
}
__device__ __forceinline__ void ldmatrix_x2_trans(uint32_t* r, uint32_t addr) {
  asm volatile(
      "ldmatrix.sync.aligned.m8n8.x2.trans.shared.b16 {%0,%1}, [%2];\n"
      : "=r"(r[0]), "=r"(r[1])
      : "r"(addr));
}
__device__ __forceinline__ void ldmatrix_x4_trans(uint32_t* r, uint32_t addr) {
  asm volatile(
      "ldmatrix.sync.aligned.m8n8.x4.trans.shared.b16 {%0,%1,%2,%3}, [%4];\n"
      : "=r"(r[0]), "=r"(r[1]), "=r"(r[2]), "=r"(r[3])
      : "r"(addr));
}

__device__ __forceinline__ void mma_bf16(float* c, const uint32_t* a,
                                         uint32_t b0, uint32_t b1) {
  asm volatile(
      "mma.sync.aligned.m16n8k16.row.col.f32.bf16.bf16.f32 "
      "{%0,%1,%2,%3}, {%4,%5,%6,%7}, {%8,%9}, {%0,%1,%2,%3};\n"
      : "+f"(c[0]), "+f"(c[1]), "+f"(c[2]), "+f"(c[3])
      : "r"(a[0]), "r"(a[1]), "r"(a[2]), "r"(a[3]), "r"(b0), "r"(b1));
}

// bf16 split-pack: hi pair returned (f0 low half), lo pair in lo_out.
__device__ __forceinline__ uint32_t pack_split_bf16(float f0, float f1,
                                                    uint32_t& lo_out) {
  uint32_t hi;
  asm("cvt.rn.bf16x2.f32 %0, %1, %2;\n" : "=r"(hi) : "f"(f1), "f"(f0));
  const float h0 = __uint_as_float(hi << 16);
  const float h1 = __uint_as_float(hi & 0xFFFF0000u);
  const float l0 = f0 - h0;
  const float l1 = f1 - h1;
  asm("cvt.rn.bf16x2.f32 %0, %1, %2;\n" : "=r"(lo_out) : "f"(l1), "f"(l0));
  return hi;
}

// ---------------------------------------------------------------------------
// Prepack: fp32 -> bf16 hi/lo planes.
// ---------------------------------------------------------------------------
__global__ void split_kernel(const float* __restrict__ in,
                             __nv_bfloat16* __restrict__ hi,
                             __nv_bfloat16* __restrict__ lo) {
  const int i = blockIdx.x * blockDim.x + threadIdx.x;
  const float2 v = ((const float2*)in)[i];
  uint32_t l;
  const uint32_t h = pack_split_bf16(v.x, v.y, l);
  ((uint32_t*)hi)[i] = h;
  ((uint32_t*)lo)[i] = l;
}

// ---------------------------------------------------------------------------
// bf16x3 GEMM mainloop (R11 winner): 256 threads, 8 warps (64x32 warp tile),
// BK=64, 3 smem stages, x4_trans B fragments. A planes [M][K], B planes [K][N].
// ---------------------------------------------------------------------------
struct MmaCtx {
  float acc[4][4][4];
};

template <int K, int N>
__device__ __forceinline__ void bf16_mainloop(
    const __nv_bfloat16* __restrict__ Ahp, const __nv_bfloat16* __restrict__ Alp,
    const __nv_bfloat16* __restrict__ Bhp, const __nv_bfloat16* __restrict__ Blp,
    int m0, int n0, char* sm, MmaCtx& ctx) {
  const int tid = threadIdx.x;
  const int lane = tid & 31;
  const int wid = tid >> 5;
  const int wm = wid & 1;   // 0..1 (64-row slabs)
  const int wn = wid >> 1;  // 0..3 (32-col slabs)

#pragma unroll
  for (int mt = 0; mt < 4; mt++)
#pragma unroll
    for (int nt = 0; nt < 4; nt++)
#pragma unroll
      for (int r = 0; r < 4; r++) ctx.acc[mt][nt][r] = 0.f;

  const int kTiles = K / BK;

  auto load_stage = [&](int t, int buf) {
    const int k0 = t * BK;
    const uint32_t base = smem_u32(sm) + (uint32_t)buf * STAGE_BYTES;
#pragma unroll
    for (int i = 0; i < 4; i++) {
      const int idx = tid + i * 256;
      const int ar = idx >> 3, akc = (idx & 7) * 8;
      cp_async16(base + (ar * AHSTR + akc) * 2,
                 Ahp + (size_t)(m0 + ar) * K + k0 + akc);
      cp_async16(base + APLANE + (ar * AHSTR + akc) * 2,
                 Alp + (size_t)(m0 + ar) * K + k0 + akc);
      const int br = idx >> 4, bnc = (idx & 15) * 8;
      cp_async16(base + 2 * APLANE + (br * BHSTR + bnc) * 2,
                 Bhp + (size_t)(k0 + br) * N + n0 + bnc);
      cp_async16(base + 2 * APLANE + BPLANE + (br * BHSTR + bnc) * 2,
                 Blp + (size_t)(k0 + br) * N + n0 + bnc);
    }
    cp_commit();
  };

  load_stage(0, 0);
  load_stage(1, 1);

  const int lrow = lane & 15;
  const int lseg = (lane >> 4) * 8;
  const int bkrow = ((lane >> 3) & 1) * 8 + (lane & 7);
  const int bnseg = (lane >> 4) * 8;

  for (int t = 0; t < kTiles; t++) {
    const int buf = t % NSTAGE;
    if (t + 2 < kTiles) cp_wait<1>();
    else cp_wait<0>();
    __syncthreads();   // stage t visible; all warps done reading buf (t-1)

    if (t + 2 < kTiles) load_stage(t + 2, (t + 2) % NSTAGE);

    const uint32_t ahu = smem_u32(sm) + (uint32_t)buf * STAGE_BYTES;
    const uint32_t alu = ahu + APLANE;
    const uint32_t bhu = ahu + 2 * APLANE;
    const uint32_t blu = bhu + BPLANE;

#pragma unroll
    for (int ks = 0; ks < 4; ks++) {
      uint32_t ah[4][4], al[4][4];
#pragma unroll
      for (int mt = 0; mt < 4; mt++) {
        const int row = wm * 64 + mt * 16 + lrow;
        const uint32_t off = (uint32_t)(row * AHSTR + ks * 16 + lseg) * 2;
        ldmatrix_x4(ah[mt], ahu + off);
        ldmatrix_x4(al[mt], alu + off);
      }
      uint32_t bh[4][2], bl[4][2];
#pragma unroll
      for (int np = 0; np < 2; np++) {
        const uint32_t off =
            (uint32_t)((ks * 16 + bkrow) * BHSTR + wn * 32 + np * 16 + bnseg) * 2;
        uint32_t rh[4], rl[4];
        ldmatrix_x4_trans(rh, bhu + off);
        ldmatrix_x4_trans(rl, blu + off);
        bh[2 * np][0] = rh[0]; bh[2 * np][1] = rh[1];
        bh[2 * np + 1][0] = rh[2]; bh[2 * np + 1][1] = rh[3];
        bl[2 * np][0] = rl[0]; bl[2 * np][1] = rl[1];
        bl[2 * np + 1][0] = rl[2]; bl[2 * np + 1][1] = rl[3];
      }
#pragma unroll
      for (int mt = 0; mt < 4; mt++)
#pragma unroll
        for (int nt = 0; nt < 4; nt++) {
          mma_bf16(ctx.acc[mt][nt], al[mt], bh[nt][0], bh[nt][1]);
          mma_bf16(ctx.acc[mt][nt], ah[mt], bl[nt][0], bl[nt][1]);
          mma_bf16(ctx.acc[mt][nt], ah[mt], bh[nt][0], bh[nt][1]);
        }
    }
  }
}

// ---------------------------------------------------------------------------
// Kernel 1: qkv = x @ w_qkv + b_qkv -> bf16 hi/lo planes of Q(scaled),K,V
// ---------------------------------------------------------------------------
__global__ __launch_bounds__(256, 1) void qkv_gemm_kernel(
    const float* __restrict__ bias) {
  extern __shared__ char sm[];
  const int m0 = blockIdx.y * BM;
  const int n0 = blockIdx.x * BN;

  MmaCtx ctx;
  bf16_mainloop<D_, NQKV>(g_Xh, g_Xl, g_Wh, g_Wl, m0, n0, sm, ctx);

  const int lane = threadIdx.x & 31;
  const int wid = threadIdx.x >> 5;
  const int wm = wid & 1, wn = wid >> 1;

#pragma unroll
  for (int nt = 0; nt < 4; nt++) {
    const int n = n0 + wn * 32 + nt * 8 + (lane & 3) * 2;
    const int t = n >> 10;
    const int rem = n & 1023;
    const int h = rem >> 6;
    const int e = rem & 63;
    __nv_bfloat16* dh = (t == 0) ? g_Qh : (t == 1) ? g_Kh : g_Vh;
    __nv_bfloat16* dl = (t == 0) ? g_Ql : (t == 1) ? g_Kl : g_Vl;
    const float sc = (t == 0) ? 0.125f : 1.0f;
    const float bz0 = bias[n], bz1 = bias[n + 1];
#pragma unroll
    for (int mt = 0; mt < 4; mt++) {
      const int mbase = m0 + wm * 64 + mt * 16 + (lane >> 2);
#pragma unroll
      for (int half = 0; half < 2; half++) {
        const int m = mbase + half * 8;
        const int b = m >> 11;
        const int s = m & 2047;
        const float v0 = (ctx.acc[mt][nt][half * 2 + 0] + bz0) * sc;
        const float v1 = (ctx.acc[mt][nt][half * 2 + 1] + bz1) * sc;
        uint32_t lo;
        const uint32_t hi = pack_split_bf16(v0, v1, lo);
        const size_t idx = (((size_t)(b * H_ + h) * S_ + s) * DH_ + e) >> 1;
        ((uint32_t*)dh)[idx] = hi;
        ((uint32_t*)dl)[idx] = lo;
      }
    }
  }
}

// ---------------------------------------------------------------------------
// Kernel 3: out = O @ w_out + b_out (reads bf16 planes, writes fp32)
// ---------------------------------------------------------------------------
__global__ __launch_bounds__(256, 1) void out_gemm_kernel(
    const float* __restrict__ bias, float* __restrict__ out) {
  extern __shared__ char sm[];
  const int m0 = blockIdx.y * BM;
  const int n0 = blockIdx.x * BN;

  MmaCtx ctx;
  bf16_mainloop<D_, D_>(g_Oh, g_Ol, g_WOh, g_WOl, m0, n0, sm, ctx);

  const int lane = threadIdx.x & 31;
  const int wid = threadIdx.x >> 5;
  const int wm = wid & 1, wn = wid >> 1;

#pragma unroll
  for (int nt = 0; nt < 4; nt++) {
    const int n = n0 + wn * 32 + nt * 8 + (lane & 3) * 2;
    const float bz0 = bias[n], bz1 = bias[n + 1];
#pragma unroll
    for (int mt = 0; mt < 4; mt++) {
      const int mbase = m0 + wm * 64 + mt * 16 + (lane >> 2);
#pragma unroll
      for (int half = 0; half < 2; half++) {
        const int m = mbase + half * 8;
        float2 v;
        v.x = ctx.acc[mt][nt][half * 2 + 0] + bz0;
        v.y = ctx.acc[mt][nt][half * 2 + 1] + bz1;
        *(float2*)&out[(size_t)m * D_ + n] = v;
      }
    }
  }
}

// ---------------------------------------------------------------------------
// Kernel 2: causal flash attention, bf16x3, P in registers. K/V loaded in
// 128-row double-buffered tiles; each tile processed as two 64-row halves
// with identical arithmetic to the R9-R12 winner (half the barriers).
// ---------------------------------------------------------------------------
__global__ __launch_bounds__(256, 1) void attn_kernel() {
  extern __shared__ char smc[];
  __nv_bfloat16* Qh = (__nv_bfloat16*)smc;
  __nv_bfloat16* Ql = (__nv_bfloat16*)(smc + QPLANE);
  const uint32_t qh_u = smem_u32(Qh), ql_u = smem_u32(Ql);
  const uint32_t kv_u = smem_u32(smc + 2 * QPLANE);

  const int tid = threadIdx.x;
  const int lane = tid & 31;
  const int w = tid >> 5;
  const int g = lane >> 2;
  const int t = lane & 3;
  const int qt = (int)gridDim.x - 1 - (int)blockIdx.x;  // long CTAs first
  const int q0 = qt * 128;
  const int bh = blockIdx.y;
  const int b = bh >> 4, h = bh & 15;
  const size_t base = (size_t)bh * S_ * DH_;

  // 128-row K/V tile loader: 4 planes x 128 rows x 64 cols = 4096 16B chunks
  auto load_kv = [&](int bt, int buf) {
    const int k0 = bt * 128;
    const uint32_t kb = kv_u + (uint32_t)buf * KVBUF;
#pragma unroll
    for (int it = 0; it < 16; it++) {
      const int idx = tid + it * 256;
      const int pl = idx >> 10;                 // 1024 chunks per plane
      const int r = (idx >> 3) & 127, c = (idx & 7) * 8;
      const __nv_bfloat16* src = (pl == 0) ? g_Kh : (pl == 1) ? g_Kl
                               : (pl == 2) ? g_Vh : g_Vl;
      cp_async16(kb + (uint32_t)(pl * KVPLANE) + (uint32_t)(r * QSTR + c) * 2,
                 src + base + (size_t)(k0 + r) * DH_ + c);
    }
    cp_commit();
  };

  load_kv(0, 0);

  // Stage Q planes (scaled by 0.125 at qkv epilogue)
#pragma unroll
  for (int it = 0; it < 8; it++) {
    const int idx = tid + it * 256;
    const int pl = idx >> 10;
    const int r = (idx >> 3) & 127, c = (idx & 7) * 8;
    const __nv_bfloat16* src = pl ? g_Ql : g_Qh;
    __nv_bfloat16* dst = pl ? Ql : Qh;
    *(uint4*)&dst[r * QSTR + c] = *(const uint4*)&src[base + (size_t)(q0 + r) * DH_ + c];
  }
  __syncthreads();

  uint32_t qfh[4][4], qfl[4][4];
  {
    const int row = w * 16 + (lane & 15);
    const int seg = (lane >> 4) * 8;
#pragma unroll
    for (int ks = 0; ks < 4; ks++) {
      const uint32_t off = (uint32_t)(row * QSTR + ks * 16 + seg) * 2;
      ldmatrix_x4(qfh[ks], qh_u + off);
      ldmatrix_x4(qfl[ks], ql_u + off);
    }
  }

  float m_a = -1e30f, m_b = -1e30f, l_a = 0.f, l_b = 0.f;
  float o[8][4];
#pragma unroll
  for (int nt = 0; nt < 8; nt++)
#pragma unroll
    for (int r = 0; r < 4; r++) o[nt][r] = 0.f;

  const int nbt = qt + 1;                       // 128-row K/V tiles
  const int lr = w * 16 + g;
  for (int bt = 0; bt < nbt; bt++) {
    const int buf = bt & 1;
    cp_wait<0>();      // K/V tile bt resident
    __syncthreads();   // visible to all; prior compute on buf^1 done

    if (bt + 1 < nbt) load_kv(bt + 1, buf ^ 1);

    const uint32_t kb = kv_u + (uint32_t)buf * KVBUF;

#pragma unroll
    for (int hf = 0; hf < 2; hf++) {
      const uint32_t kh_u = kb + (uint32_t)hf * KVHALF;
      const uint32_t kl_u = kh_u + KVPLANE;
      const uint32_t vh_u = kb + 2 * KVPLANE + (uint32_t)hf * KVHALF;
      const uint32_t vl_u = vh_u + KVPLANE;
      const int k0 = bt * 128 + hf * 64;

      float s[8][4];
#pragma unroll
      for (int nt = 0; nt < 8; nt++) {
#pragma unroll
        for (int r = 0; r < 4; r++) s[nt][r] = 0.f;
        const uint32_t roff =
            (uint32_t)((nt * 8 + (lane & 7)) * QSTR + ((lane >> 3) & 1) * 8) * 2;
#pragma unroll
        for (int ks = 0; ks < 4; ks++) {
          uint32_t kbh[2], kbl[2];
          const uint32_t off = roff + (uint32_t)(ks * 16) * 2;
          ldmatrix_x2(kbh, kh_u + off);
          ldmatrix_x2(kbl, kl_u + off);
          mma_bf16(s[nt], qfl[ks], kbh[0], kbh[1]);
          mma_bf16(s[nt], qfh[ks], kbl[0], kbl[1]);
          mma_bf16(s[nt], qfh[ks], kbh[0], kbh[1]);
        }
      }

      // Causal mask: only the diagonal 128x128 block (bt == nbt-1)
      if (bt == nbt - 1) {
        const int ra = q0 + lr, rb = ra + 8;
#pragma unroll
        for (int nt = 0; nt < 8; nt++) {
          const int c0 = k0 + nt * 8 + t * 2;
          if (c0 > ra) s[nt][0] = -1e30f;
          if (c0 + 1 > ra) s[nt][1] = -1e30f;
          if (c0 > rb) s[nt][2] = -1e30f;
          if (c0 + 1 > rb) s[nt][3] = -1e30f;
        }
      }

      // Online softmax (row groups = 4 lanes)
      float mxa = -1e30f, mxb = -1e30f;
#pragma unroll
      for (int nt = 0; nt < 8; nt++) {
        mxa = fmaxf(mxa, fmaxf(s[nt][0], s[nt][1]));
        mxb = fmaxf(mxb, fmaxf(s[nt][2], s[nt][3]));
      }
#pragma unroll
      for (int off = 1; off <= 2; off <<= 1) {
        mxa = fmaxf(mxa, __shfl_xor_sync(0xffffffffu, mxa, off));
        mxb = fmaxf(mxb, __shfl_xor_sync(0xffffffffu, mxb, off));
      }
      const float mna = fmaxf(m_a, mxa), mnb = fmaxf(m_b, mxb);
      const float sca = __expf(m_a - mna), scb = __expf(m_b - mnb);
      float rsa = 0.f, rsb = 0.f;
#pragma unroll
      for (int nt = 0; nt < 8; nt++) {
        s[nt][0] = __expf(s[nt][0] - mna);
        s[nt][1] = __expf(s[nt][1] - mna);
        s[nt][2] = __expf(s[nt][2] - mnb);
        s[nt][3] = __expf(s[nt][3] - mnb);
        rsa += s[nt][0] + s[nt][1];
        rsb += s[nt][2] + s[nt][3];
      }
#pragma unroll
      for (int off = 1; off <= 2; off <<= 1) {
        rsa += __shfl_xor_sync(0xffffffffu, rsa, off);
        rsb += __shfl_xor_sync(0xffffffffu, rsb, off);
      }
      l_a = l_a * sca + rsa;
      l_b = l_b * scb + rsb;
      m_a = mna;
      m_b = mnb;
#pragma unroll
      for (int nt = 0; nt < 8; nt++) {
        o[nt][0] *= sca; o[nt][1] *= sca;
        o[nt][2] *= scb; o[nt][3] *= scb;
      }

      // O += P V (P C-frag == A-frag; split P to bf16 hi/lo in regs)
#pragma unroll
      for (int jt = 0; jt < 4; jt++) {
        uint32_t ph[4], pl[4];
        ph[0] = pack_split_bf16(s[2 * jt][0], s[2 * jt][1], pl[0]);
        ph[1] = pack_split_bf16(s[2 * jt][2], s[2 * jt][3], pl[1]);
        ph[2] = pack_split_bf16(s[2 * jt + 1][0], s[2 * jt + 1][1], pl[2]);
        ph[3] = pack_split_bf16(s[2 * jt + 1][2], s[2 * jt + 1][3], pl[3]);
        const uint32_t roff = (uint32_t)((jt * 16 + (lane & 15)) * QSTR) * 2;
#pragma unroll
        for (int nt = 0; nt < 8; nt++) {
          uint32_t vbh[2], vbl[2];
          const uint32_t off = roff + (uint32_t)(nt * 8) * 2;
          ldmatrix_x2_trans(vbh, vh_u + off);
          ldmatrix_x2_trans(vbl, vl_u + off);
          mma_bf16(o[nt], pl, vbh[0], vbh[1]);
          mma_bf16(o[nt], ph, vbl[0], vbl[1]);
          mma_bf16(o[nt], ph, vbh[0], vbh[1]);
        }
      }
    }
  }

  // Epilogue: normalize, split to bf16 hi/lo O planes [B,S,H,DH]
  const float ia = 1.f / l_a, ib = 1.f / l_b;
  const int ra = q0 + lr, rb = ra + 8;
#pragma unroll
  for (int nt = 0; nt < 8; nt++) {
    const int e = nt * 8 + t * 2;
    uint32_t lo;
    uint32_t hi = pack_split_bf16(o[nt][0] * ia, o[nt][1] * ia, lo);
    size_t idx = (((size_t)(b * S_ + ra) * H_ + h) * DH_ + e) >> 1;
    ((uint32_t*)g_Oh)[idx] = hi;
    ((uint32_t*)g_Ol)[idx] = lo;
    hi = pack_split_bf16(o[nt][2] * ib, o[nt][3] * ib, lo);
    idx = (((size_t)(b * S_ + rb) * H_ + h) * DH_ + e) >> 1;
    ((uint32_t*)g_Oh)[idx] = hi;
    ((uint32_t*)g_Ol)[idx] = lo;
  }
}

// ---------------------------------------------------------------------------
extern "C" void kernel_launch(void* const* d_in, const int* in_sizes, int n_in,
                              void* d_out, int out_size) {
  const float* x     = (const float*)d_in[0];  // [B,S,D]
  const float* w_qkv = (const float*)d_in[1];  // [D,3,H,DH]
  const float* b_qkv = (const float*)d_in[2];  // [3,H,DH]
  const float* w_out = (const float*)d_in[3];  // [H,DH,D]
  const float* b_out = (const float*)d_in[4];  // [D]
  float* out = (float*)d_out;                  // [B,S,D]

  cudaFuncSetAttribute(qkv_gemm_kernel,
                       cudaFuncAttributeMaxDynamicSharedMemorySize,
                       GEMM_SMEM_BYTES);
  cudaFuncSetAttribute(out_gemm_kernel,
                       cudaFuncAttributeMaxDynamicSharedMemorySize,
                       GEMM_SMEM_BYTES);
  cudaFuncSetAttribute(attn_kernel, cudaFuncAttributeMaxDynamicSharedMemorySize,
                       ATTN_SMEM_BYTES);

  __nv_bfloat16 *xh, *xl, *wh, *wl, *woh, *wol;
  cudaGetSymbolAddress((void**)&xh, g_Xh);
  cudaGetSymbolAddress((void**)&xl, g_Xl);
  cudaGetSymbolAddress((void**)&wh, g_Wh);
  cudaGetSymbolAddress((void**)&wl, g_Wl);
  cudaGetSymbolAddress((void**)&woh, g_WOh);
  cudaGetSymbolAddress((void**)&wol, g_WOl);

  split_kernel<<<(M_ * D_ / 2) / 256, 256>>>(x, xh, xl);
  split_kernel<<<(D_ * NQKV / 2) / 256, 256>>>(w_qkv, wh, wl);
  split_kernel<<<(D_ * D_ / 2) / 256, 256>>>(w_out, woh, wol);

  qkv_gemm_kernel<<<dim3(NQKV / BN, M_ / BM), 256, GEMM_SMEM_BYTES>>>(b_qkv);
  attn_kernel<<<dim3(S_ / 128, B_ * H_), 256, ATTN_SMEM_BYTES>>>();
  out_gemm_kernel<<<dim3(D_ / BN, M_ / BM), 256, GEMM_SMEM_BYTES>>>(b_out, out);
}